// round 14
// baseline (speedup 1.0000x reference)
#include <cuda_runtime.h>

#define NN 100000
#define EE 1600000
#define DDIM 8
#define HDIM 256

// ---- node data ----
__device__ float4 g_qn  [NN*2];   // q * norm_src
__device__ float4 g_t1  [NN*2];   // (gathered qn) * norm_dst
__device__ float4 g_vn  [NN*2];   // v * norm_src
__device__ float4 g_hm  [NN*4];   // packed per node: h2[0], h2[1], md[0], md[1]
__device__ float4 g_G   [NN*2];
__device__ float4 g_Gn  [NN*2];   // G * norm_dst
__device__ float4 g_rn  [NN*2];   // (gathered Gn) * norm_src
__device__ float4 g_zzn [NN*2];   // zz * norm_dst
__device__ float  g_norm_src[NN];
__device__ float  g_norm_dst[NN];
__device__ unsigned g_mask[NN*DDIM];
// ---- CSR (zero at load; counters restored each call) ----
__device__ int   g_degout[NN], g_degin[NN];
__device__ int   g_rowQ[NN], g_rowS[NN];
__device__ int   g_curQ[NN], g_curS[NN];
__device__ int   g_colQ[EE];
__device__ int   g_colS[EE];
__device__ int   g_ctrQ, g_ctrS;

__device__ __forceinline__ float4 f4add(float4 a, float4 b) {
    return make_float4(a.x+b.x, a.y+b.y, a.z+b.z, a.w+b.w);
}
__device__ __forceinline__ float4 f4scale(float4 a, float s) {
    return make_float4(a.x*s, a.y*s, a.z*s, a.w*s);
}
__device__ __forceinline__ void pdl_wait() { cudaGridDependencySynchronize(); }

// 1) degree count
__global__ void k_deg(const int* __restrict__ src, const int* __restrict__ dst, int E) {
    int e = blockIdx.x * blockDim.x + threadIdx.x;
    if (e >= E) return;
    atomicAdd(&g_degout[src[e]], 1);
    atomicAdd(&g_degin [dst[e]], 1);
}

// 2) norms, CSR row alloc, md (packed into hm), qn, dHdP
__global__ void k_prep(const float* __restrict__ p, const float* __restrict__ M,
                       const float* __restrict__ q, float4* __restrict__ out4, int n) {
    int nd = blockIdx.x * blockDim.x + threadIdx.x;
    int lane = threadIdx.x & 31;
    bool act = nd < n;
    float md[8];
    float4 qa = make_float4(0,0,0,0), qb = qa, pa = qa, pb = qa;
    if (act) {
        const float* Mr = M + (long long)nd * 64;
#pragma unroll
        for (int d = 0; d < 8; d++) md[d] = Mr[d * 9];
        const float4* q4 = (const float4*)q;
        const float4* p4 = (const float4*)p;
        qa = q4[nd*2]; qb = q4[nd*2+1];
        pa = p4[nd*2]; pb = p4[nd*2+1];
    }
    pdl_wait();
    int din  = act ? g_degin[nd]  : 0;
    int dout = act ? g_degout[nd] : 0;
    int sin = din, sout = dout;
#pragma unroll
    for (int o = 1; o < 32; o <<= 1) {
        int t1 = __shfl_up_sync(0xFFFFFFFFu, sin,  o); if (lane >= o) sin  += t1;
        int t2 = __shfl_up_sync(0xFFFFFFFFu, sout, o); if (lane >= o) sout += t2;
    }
    int baseQ = 0, baseS = 0;
    if (lane == 31) {
        baseQ = atomicAdd(&g_ctrQ, sin);
        baseS = atomicAdd(&g_ctrS, sout);
    }
    baseQ = __shfl_sync(0xFFFFFFFFu, baseQ, 31);
    baseS = __shfl_sync(0xFFFFFFFFu, baseS, 31);
    if (!act) return;
    int rowQ = baseQ + sin - din;
    int rowS = baseS + sout - dout;
    g_rowQ[nd] = rowQ; g_curQ[nd] = rowQ;
    g_rowS[nd] = rowS; g_curS[nd] = rowS;

    float nsrc = (dout > 0) ? rsqrtf((float)dout) : 1.0f;
    float ndst = (din  > 0) ? rsqrtf((float)din)  : 1.0f;
    g_norm_src[nd] = nsrc;
    g_norm_dst[nd] = ndst;
    g_hm[nd*4+2] = make_float4(md[0], md[1], md[2], md[3]);
    g_hm[nd*4+3] = make_float4(md[4], md[5], md[6], md[7]);
    g_qn[nd*2]   = f4scale(qa, nsrc);
    g_qn[nd*2+1] = f4scale(qb, nsrc);
    out4[nd*4+2] = make_float4(pa.x/md[0], pa.y/md[1], pa.z/md[2], pa.w/md[3]);
    out4[nd*4+3] = make_float4(pb.x/md[4], pb.y/md[5], pb.z/md[6], pb.w/md[7]);
}

// 3) build both CSRs — 2 threads per edge (one per side)
__global__ void k_fill(const int* __restrict__ src, const int* __restrict__ dst, int E) {
    int t = blockIdx.x * blockDim.x + threadIdx.x;
    int e = t >> 1, side = t & 1;
    int s = 0, u = 0;
    bool act = e < E;
    if (act) { s = src[e]; u = dst[e]; }
    pdl_wait();
    if (!act) return;
    if (side == 0) g_colQ[atomicAdd(&g_curQ[u], 1)] = s;
    else           g_colS[atomicAdd(&g_curS[s], 1)] = u;
}

// 4) t1[n] = (sum over in-edges qn[src]) * ndst
//    2 lanes per node: lane j loads ONLY float4 #j of each visited 32B record
//    → both lanes hit the same 128B line → 1 payload wavefront per visit.
__global__ void k_aggT1(int n2) {
    pdl_wait();
    int i = blockIdx.x * blockDim.x + threadIdx.x;
    bool ok = i < n2;
    int node = ok ? (i >> 1) : 0;
    int j = i & 1;
    int row = g_rowQ[node];
    int len = ok ? g_degin[node] : 0;
    float4 acc = make_float4(0.f, 0.f, 0.f, 0.f);
    for (int k = 0; k < len; k++) {
        int s = __ldg(&g_colQ[row + k]);
        acc = f4add(acc, __ldg(&g_qn[s*2 + j]));
    }
    if (!ok) return;
    g_t1[i] = f4scale(acc, g_norm_dst[node]);
}

// 5) MLP fwd: register weights (1 block/SM cap — 148 blocks = exactly 1 wave)
__global__ __launch_bounds__(256) void k_mlp_fwd(
        const float* __restrict__ W1v, const float* __restrict__ b1v,
        const float* __restrict__ W2v, int n, int totalWarps) {
    int tid = blockIdx.x * blockDim.x + threadIdx.x;
    int gw = tid >> 5, lane = tid & 31;

    float w1r[8][8], w2r[8][8], b1r[8];
#pragma unroll
    for (int u = 0; u < 8; u++) {
        int j = u * 32 + lane;
#pragma unroll
        for (int d = 0; d < 8; d++) w1r[u][d] = __ldg(&W1v[d * HDIM + j]);
        float4 wa = __ldg((const float4*)(W2v + j * 8));
        float4 wb = __ldg((const float4*)(W2v + j * 8 + 4));
        w2r[u][0] = wa.x; w2r[u][1] = wa.y; w2r[u][2] = wa.z; w2r[u][3] = wa.w;
        w2r[u][4] = wb.x; w2r[u][5] = wb.y; w2r[u][6] = wb.z; w2r[u][7] = wb.w;
        b1r[u] = __ldg(&b1v[j]);
    }
    pdl_wait();

    int node = gw;
    float4 ca = make_float4(0,0,0,0), cb = ca;
    if (node < n) { ca = __ldg(&g_t1[node*2]); cb = __ldg(&g_t1[node*2+1]); }
    for (; node < n; node += totalWarps) {
        int nxt = node + totalWarps;
        float4 na = make_float4(0,0,0,0), nb = na;
        if (nxt < n) { na = __ldg(&g_t1[nxt*2]); nb = __ldg(&g_t1[nxt*2+1]); }
        float t1[8] = {ca.x, ca.y, ca.z, ca.w, cb.x, cb.y, cb.z, cb.w};
        float acc[8] = {0.f,0.f,0.f,0.f,0.f,0.f,0.f,0.f};
#pragma unroll
        for (int u = 0; u < 8; u++) {
            float h = b1r[u];
#pragma unroll
            for (int d = 0; d < 8; d++) h = fmaf(t1[d], w1r[u][d], h);
            unsigned m = __ballot_sync(0xFFFFFFFFu, h > 0.f);
            if (lane == 0) g_mask[node * 8 + u] = m;
            h = (h > 0.f) ? h : 0.f;
#pragma unroll
            for (int d = 0; d < 8; d++) acc[d] = fmaf(h, w2r[u][d], acc[d]);
        }
#pragma unroll
        for (int off = 16; off; off >>= 1)
#pragma unroll
            for (int d = 0; d < 8; d++) acc[d] += __shfl_xor_sync(0xFFFFFFFFu, acc[d], off);
        if (lane == 0) {
            float ns = g_norm_src[node];
            g_vn[node*2]   = make_float4(acc[0]*ns, acc[1]*ns, acc[2]*ns, acc[3]*ns);
            g_vn[node*2+1] = make_float4(acc[4]*ns, acc[5]*ns, acc[6]*ns, acc[7]*ns);
        }
        ca = na; cb = nb;
    }
}

// 6) h2 = (gather vn over in-edges)*ndst + b2 + q  → packed g_hm; 2 lanes/node
__global__ void k_agg2h2(const float* __restrict__ q, const float* __restrict__ b2, int n2) {
    int i = blockIdx.x * blockDim.x + threadIdx.x;
    bool ok = i < n2;
    int node = ok ? (i >> 1) : 0;
    int j = i & 1;
    float4 b2h = ((const float4*)b2)[j];
    float4 qv = make_float4(0,0,0,0);
    if (ok) qv = ((const float4*)q)[i];
    pdl_wait();
    int row = g_rowQ[node];
    int len = ok ? g_degin[node] : 0;
    float4 acc = make_float4(0.f, 0.f, 0.f, 0.f);
    for (int k = 0; k < len; k++) {
        int s = __ldg(&g_colQ[row + k]);
        acc = f4add(acc, __ldg(&g_vn[s*2 + j]));
    }
    if (!ok) return;
    g_hm[node*4 + j] = f4add(f4add(f4scale(acc, g_norm_dst[node]), b2h), qv);
}

// 7) G[n] = sum over incident edges c*(h2[other]-h2[n])
//    4 lanes per node: lane m loads hm[o*4+m] (16B of the 64B record → 1 line
//    per visit). m<2 lanes compute δ partials, m>=2 compute mass-dot partials;
//    shfl_xor(1) then shfl_xor(2) assemble full e2+sm in each lane.
__global__ void k_GkC(const float* __restrict__ grav, int n) {
    float gv = 0.5f * __ldg(grav);
    pdl_wait();
    int t = blockIdx.x * blockDim.x + threadIdx.x;
    int node = t >> 2, m = t & 3;
    bool ok = node < n;
    if (!ok) node = 0;
    float4 cn = g_hm[node*4 + m];   // m0/m1: own h2 halves; m2/m3: own md halves
    int rowQ = g_rowQ[node], lenQ = ok ? g_degin[node]  : 0;
    int rowS = g_rowS[node], lenS = ok ? g_degout[node] : 0;
    float acc0 = 0.f, acc1 = 0.f, acc2 = 0.f, acc3 = 0.f;
#pragma unroll 1
    for (int pass = 0; pass < 2; pass++) {
        int row = pass ? rowS : rowQ;
        int len = pass ? lenS : lenQ;
        const int* col = pass ? g_colS : g_colQ;
        for (int k = 0; k < len; k++) {
            int o = __ldg(&col[row + k]);
            float4 ov = __ldg(&g_hm[o*4 + m]);
            float d0 = 0.f, d1 = 0.f, d2 = 0.f, d3 = 0.f;
            float partial;
            if (m < 2) {
                d0 = ov.x - cn.x; d1 = ov.y - cn.y;
                d2 = ov.z - cn.z; d3 = ov.w - cn.w;
                partial = d0*d0 + d1*d1 + d2*d2 + d3*d3;          // e2 half
            } else {
                partial = ov.x*cn.x + ov.y*cn.y + ov.z*cn.z + ov.w*cn.w;  // sm half
            }
            float sum   = partial + __shfl_xor_sync(0xFFFFFFFFu, partial, 1);
            float other = __shfl_xor_sync(0xFFFFFFFFu, sum, 2);
            float e2 = (m < 2) ? sum : other;
            float sm = (m < 2) ? other : sum;
            float inv = rsqrtf(e2);
            float c = gv * sm * inv * inv * inv;
            if (m < 2) {
                acc0 = fmaf(c, d0, acc0); acc1 = fmaf(c, d1, acc1);
                acc2 = fmaf(c, d2, acc2); acc3 = fmaf(c, d3, acc3);
            }
        }
    }
    if (!ok || m >= 2) return;
    float nd = g_norm_dst[node];
    g_G [node*2 + m] = make_float4(acc0, acc1, acc2, acc3);
    g_Gn[node*2 + m] = make_float4(acc0*nd, acc1*nd, acc2*nd, acc3*nd);
}

// 8) rn[n] = (sum over out-edges Gn[dst]) * nsrc ; 2 lanes/node
__global__ void k_aggRN(int n2) {
    pdl_wait();
    int i = blockIdx.x * blockDim.x + threadIdx.x;
    bool ok = i < n2;
    int node = ok ? (i >> 1) : 0;
    int j = i & 1;
    int row = g_rowS[node];
    int len = ok ? g_degout[node] : 0;
    float4 acc = make_float4(0.f, 0.f, 0.f, 0.f);
    for (int k = 0; k < len; k++) {
        int u = __ldg(&g_colS[row + k]);
        acc = f4add(acc, __ldg(&g_Gn[u*2 + j]));
    }
    if (!ok) return;
    g_rn[i] = f4scale(acc, g_norm_src[node]);
}

// 9) MLP bwd: register weights, 148 blocks, prefetch, writes zzn
__global__ __launch_bounds__(256) void k_mlp_bwd(
        const float* __restrict__ W1v, const float* __restrict__ W2v,
        int n, int totalWarps) {
    int tid = blockIdx.x * blockDim.x + threadIdx.x;
    int gw = tid >> 5, lane = tid & 31;

    float w1r[8][8], w2r[8][8];
#pragma unroll
    for (int u = 0; u < 8; u++) {
        int j = u * 32 + lane;
#pragma unroll
        for (int d = 0; d < 8; d++) w1r[u][d] = __ldg(&W1v[d * HDIM + j]);
        float4 wa = __ldg((const float4*)(W2v + j * 8));
        float4 wb = __ldg((const float4*)(W2v + j * 8 + 4));
        w2r[u][0] = wa.x; w2r[u][1] = wa.y; w2r[u][2] = wa.z; w2r[u][3] = wa.w;
        w2r[u][4] = wb.x; w2r[u][5] = wb.y; w2r[u][6] = wb.z; w2r[u][7] = wb.w;
    }
    pdl_wait();

    int node = gw;
    float4 ca = make_float4(0,0,0,0), cb = ca;
    unsigned cm[8] = {0,0,0,0,0,0,0,0};
    if (node < n) {
        ca = __ldg(&g_rn[node*2]); cb = __ldg(&g_rn[node*2+1]);
#pragma unroll
        for (int u = 0; u < 8; u++) cm[u] = __ldg(&g_mask[node*8+u]);
    }
    for (; node < n; node += totalWarps) {
        int nxt = node + totalWarps;
        float4 na = make_float4(0,0,0,0), nb = na;
        unsigned nm[8] = {0,0,0,0,0,0,0,0};
        if (nxt < n) {
            na = __ldg(&g_rn[nxt*2]); nb = __ldg(&g_rn[nxt*2+1]);
#pragma unroll
            for (int u = 0; u < 8; u++) nm[u] = __ldg(&g_mask[nxt*8+u]);
        }
        float rr[8] = {ca.x, ca.y, ca.z, ca.w, cb.x, cb.y, cb.z, cb.w};
        float acc[8] = {0.f,0.f,0.f,0.f,0.f,0.f,0.f,0.f};
#pragma unroll
        for (int u = 0; u < 8; u++) {
            float gh = 0.f;
#pragma unroll
            for (int d = 0; d < 8; d++) gh = fmaf(rr[d], w2r[u][d], gh);
            float gu = ((cm[u] >> lane) & 1u) ? gh : 0.f;
#pragma unroll
            for (int d = 0; d < 8; d++) acc[d] = fmaf(gu, w1r[u][d], acc[d]);
        }
#pragma unroll
        for (int off = 16; off; off >>= 1)
#pragma unroll
            for (int d = 0; d < 8; d++) acc[d] += __shfl_xor_sync(0xFFFFFFFFu, acc[d], off);
        if (lane == 0) {
            float ndst = g_norm_dst[node];
            g_zzn[node*2]   = make_float4(acc[0]*ndst, acc[1]*ndst, acc[2]*ndst, acc[3]*ndst);
            g_zzn[node*2+1] = make_float4(acc[4]*ndst, acc[5]*ndst, acc[6]*ndst, acc[7]*ndst);
        }
        ca = na; cb = nb;
#pragma unroll
        for (int u = 0; u < 8; u++) cm[u] = nm[u];
    }
}

// 10) w = gather zzn over out-edges; out = G + nsrc*w ; 2 lanes/node; reset state
__global__ void k_wfinal(float4* __restrict__ out4, int n2) {
    pdl_wait();
    int i = blockIdx.x * blockDim.x + threadIdx.x;
    bool ok = i < n2;
    int node = ok ? (i >> 1) : 0;
    int j = i & 1;
    int row = g_rowS[node];
    int len = ok ? g_degout[node] : 0;
    float4 acc = make_float4(0.f, 0.f, 0.f, 0.f);
    for (int k = 0; k < len; k++) {
        int u = __ldg(&g_colS[row + k]);
        acc = f4add(acc, __ldg(&g_zzn[u*2 + j]));
    }
    if (i == 0) { g_ctrQ = 0; g_ctrS = 0; }
    if (!ok) return;
    float ns = g_norm_src[node];
    out4[node*4 + j] = f4add(g_G[node*2 + j], f4scale(acc, ns));
    if (j == 0) g_degin[node] = 0; else g_degout[node] = 0;
}

// ---- host: PDL launches ----
template <typename K, typename... Args>
static inline void launch_pdl(K kern, int grid, int block, Args... args) {
    cudaLaunchConfig_t cfg = {};
    cfg.gridDim = dim3(grid);
    cfg.blockDim = dim3(block);
    cudaLaunchAttribute attr[1];
    attr[0].id = cudaLaunchAttributeProgrammaticStreamSerialization;
    attr[0].val.programmaticStreamSerializationAllowed = 1;
    cfg.attrs = attr;
    cfg.numAttrs = 1;
    cudaLaunchKernelEx(&cfg, kern, args...);
}

extern "C" void kernel_launch(void* const* d_in, const int* in_sizes, int n_in,
                              void* d_out, int out_size) {
    const float* q    = (const float*)d_in[0];
    const float* p    = (const float*)d_in[1];
    const float* M    = (const float*)d_in[2];
    const int*   src  = (const int*)  d_in[3];
    const int*   dst  = (const int*)  d_in[4];
    const float* W1   = (const float*)d_in[5];
    const float* b1   = (const float*)d_in[6];
    const float* W2   = (const float*)d_in[7];
    const float* b2   = (const float*)d_in[8];
    const float* grav = (const float*)d_in[9];
    float4* out4 = (float4*)d_out;

    int N = in_sizes[0] / DDIM;
    int E = in_sizes[3];
    if (N > NN || E > EE) return;

    int n2  = N * 2;
    int gN  = (N + 255) / 256;
    int gN2 = (n2 + 255) / 256;
    int gN4 = (N * 4 + 255) / 256;     // 4 lanes per node (GkC)
    int gE  = (E + 255) / 256;
    int gE2 = (E * 2 + 255) / 256;

    // MLP: 182 regs → hard cap 1 block/SM. 148 blocks = exactly one wave.
    int mlpBlocks = 148;
    int mlpWarps  = mlpBlocks * 8;

    k_deg<<<gE, 256>>>(src, dst, E);
    launch_pdl(k_prep,    gN,   256, p, M, q, out4, N);
    launch_pdl(k_fill,    gE2,  256, src, dst, E);
    launch_pdl(k_aggT1,   gN2,  256, n2);
    launch_pdl(k_mlp_fwd, mlpBlocks, 256, W1, b1, W2, N, mlpWarps);
    launch_pdl(k_agg2h2,  gN2,  256, q, b2, n2);
    launch_pdl(k_GkC,     gN4,  256, grav, N);
    launch_pdl(k_aggRN,   gN2,  256, n2);
    launch_pdl(k_mlp_bwd, mlpBlocks, 256, W1, W2, N, mlpWarps);
    launch_pdl(k_wfinal,  gN2,  256, out4, n2);
}

// round 15
// speedup vs baseline: 1.2225x; 1.2225x over previous
#include <cuda_runtime.h>

#define NN 100000
#define EE 1600000
#define DDIM 8
#define HDIM 256

// ---- node data ----
__device__ float4 g_qn  [NN*2];   // q * norm_src
__device__ float4 g_t1  [NN*2];   // (gathered qn) * norm_dst
__device__ float4 g_vn  [NN*2];   // v * norm_src
__device__ float4 g_hm  [NN*4];   // packed per node: h2[0], h2[1], md[0], md[1]
__device__ float4 g_G   [NN*2];
__device__ float4 g_Gn  [NN*2];   // G * norm_dst
__device__ float4 g_rn  [NN*2];   // (gathered Gn) * norm_src
__device__ float4 g_zzn [NN*2];   // zz * norm_dst
__device__ float  g_norm_src[NN];
__device__ float  g_norm_dst[NN];
__device__ unsigned g_mask[NN*DDIM];
// ---- CSR (zero at load; counters restored each call) ----
__device__ int   g_degout[NN], g_degin[NN];
__device__ int   g_rowQ[NN], g_rowS[NN];
__device__ int   g_curQ[NN], g_curS[NN];
__device__ int   g_colQ[EE];
__device__ int   g_colS[EE];
__device__ int   g_ctrQ, g_ctrS;

__device__ __forceinline__ float4 f4add(float4 a, float4 b) {
    return make_float4(a.x+b.x, a.y+b.y, a.z+b.z, a.w+b.w);
}
__device__ __forceinline__ float4 f4scale(float4 a, float s) {
    return make_float4(a.x*s, a.y*s, a.z*s, a.w*s);
}
__device__ __forceinline__ void pdl_wait() { cudaGridDependencySynchronize(); }

// 1) degree count
__global__ void k_deg(const int* __restrict__ src, const int* __restrict__ dst, int E) {
    int e = blockIdx.x * blockDim.x + threadIdx.x;
    if (e >= E) return;
    atomicAdd(&g_degout[src[e]], 1);
    atomicAdd(&g_degin [dst[e]], 1);
}

// 2) norms, CSR row alloc, md (packed into hm), qn, dHdP
__global__ void k_prep(const float* __restrict__ p, const float* __restrict__ M,
                       const float* __restrict__ q, float4* __restrict__ out4, int n) {
    int nd = blockIdx.x * blockDim.x + threadIdx.x;
    int lane = threadIdx.x & 31;
    bool act = nd < n;
    float md[8];
    float4 qa = make_float4(0,0,0,0), qb = qa, pa = qa, pb = qa;
    if (act) {
        const float* Mr = M + (long long)nd * 64;
#pragma unroll
        for (int d = 0; d < 8; d++) md[d] = Mr[d * 9];
        const float4* q4 = (const float4*)q;
        const float4* p4 = (const float4*)p;
        qa = q4[nd*2]; qb = q4[nd*2+1];
        pa = p4[nd*2]; pb = p4[nd*2+1];
    }
    pdl_wait();
    int din  = act ? g_degin[nd]  : 0;
    int dout = act ? g_degout[nd] : 0;
    int sin = din, sout = dout;
#pragma unroll
    for (int o = 1; o < 32; o <<= 1) {
        int t1 = __shfl_up_sync(0xFFFFFFFFu, sin,  o); if (lane >= o) sin  += t1;
        int t2 = __shfl_up_sync(0xFFFFFFFFu, sout, o); if (lane >= o) sout += t2;
    }
    int baseQ = 0, baseS = 0;
    if (lane == 31) {
        baseQ = atomicAdd(&g_ctrQ, sin);
        baseS = atomicAdd(&g_ctrS, sout);
    }
    baseQ = __shfl_sync(0xFFFFFFFFu, baseQ, 31);
    baseS = __shfl_sync(0xFFFFFFFFu, baseS, 31);
    if (!act) return;
    int rowQ = baseQ + sin - din;
    int rowS = baseS + sout - dout;
    g_rowQ[nd] = rowQ; g_curQ[nd] = rowQ;
    g_rowS[nd] = rowS; g_curS[nd] = rowS;

    float nsrc = (dout > 0) ? rsqrtf((float)dout) : 1.0f;
    float ndst = (din  > 0) ? rsqrtf((float)din)  : 1.0f;
    g_norm_src[nd] = nsrc;
    g_norm_dst[nd] = ndst;
    g_hm[nd*4+2] = make_float4(md[0], md[1], md[2], md[3]);
    g_hm[nd*4+3] = make_float4(md[4], md[5], md[6], md[7]);
    g_qn[nd*2]   = f4scale(qa, nsrc);
    g_qn[nd*2+1] = f4scale(qb, nsrc);
    out4[nd*4+2] = make_float4(pa.x/md[0], pa.y/md[1], pa.z/md[2], pa.w/md[3]);
    out4[nd*4+3] = make_float4(pb.x/md[4], pb.y/md[5], pb.z/md[6], pb.w/md[7]);
}

// 3) build both CSRs — 2 threads per edge (one per side)
__global__ void k_fill(const int* __restrict__ src, const int* __restrict__ dst, int E) {
    int t = blockIdx.x * blockDim.x + threadIdx.x;
    int e = t >> 1, side = t & 1;
    int s = 0, u = 0;
    bool act = e < E;
    if (act) { s = src[e]; u = dst[e]; }
    pdl_wait();
    if (!act) return;
    if (side == 0) g_colQ[atomicAdd(&g_curQ[u], 1)] = s;
    else           g_colS[atomicAdd(&g_curS[s], 1)] = u;
}

// 4) t1[n] = (sum over in-edges qn[src]) * ndst
//    2 lanes per node: lane j loads ONLY float4 #j of each visited 32B record
//    → both lanes hit the same 128B line → 1 payload wavefront per visit.
__global__ void k_aggT1(int n2) {
    pdl_wait();
    int i = blockIdx.x * blockDim.x + threadIdx.x;
    bool ok = i < n2;
    int node = ok ? (i >> 1) : 0;
    int j = i & 1;
    int row = g_rowQ[node];
    int len = ok ? g_degin[node] : 0;
    float4 acc = make_float4(0.f, 0.f, 0.f, 0.f);
    for (int k = 0; k < len; k++) {
        int s = __ldg(&g_colQ[row + k]);
        acc = f4add(acc, __ldg(&g_qn[s*2 + j]));
    }
    if (!ok) return;
    g_t1[i] = f4scale(acc, g_norm_dst[node]);
}

// 5) MLP fwd: register weights (1 block/SM cap — 148 blocks = exactly 1 wave)
__global__ __launch_bounds__(256) void k_mlp_fwd(
        const float* __restrict__ W1v, const float* __restrict__ b1v,
        const float* __restrict__ W2v, int n, int totalWarps) {
    int tid = blockIdx.x * blockDim.x + threadIdx.x;
    int gw = tid >> 5, lane = tid & 31;

    float w1r[8][8], w2r[8][8], b1r[8];
#pragma unroll
    for (int u = 0; u < 8; u++) {
        int j = u * 32 + lane;
#pragma unroll
        for (int d = 0; d < 8; d++) w1r[u][d] = __ldg(&W1v[d * HDIM + j]);
        float4 wa = __ldg((const float4*)(W2v + j * 8));
        float4 wb = __ldg((const float4*)(W2v + j * 8 + 4));
        w2r[u][0] = wa.x; w2r[u][1] = wa.y; w2r[u][2] = wa.z; w2r[u][3] = wa.w;
        w2r[u][4] = wb.x; w2r[u][5] = wb.y; w2r[u][6] = wb.z; w2r[u][7] = wb.w;
        b1r[u] = __ldg(&b1v[j]);
    }
    pdl_wait();

    int node = gw;
    float4 ca = make_float4(0,0,0,0), cb = ca;
    if (node < n) { ca = __ldg(&g_t1[node*2]); cb = __ldg(&g_t1[node*2+1]); }
    for (; node < n; node += totalWarps) {
        int nxt = node + totalWarps;
        float4 na = make_float4(0,0,0,0), nb = na;
        if (nxt < n) { na = __ldg(&g_t1[nxt*2]); nb = __ldg(&g_t1[nxt*2+1]); }
        float t1[8] = {ca.x, ca.y, ca.z, ca.w, cb.x, cb.y, cb.z, cb.w};
        float acc[8] = {0.f,0.f,0.f,0.f,0.f,0.f,0.f,0.f};
#pragma unroll
        for (int u = 0; u < 8; u++) {
            float h = b1r[u];
#pragma unroll
            for (int d = 0; d < 8; d++) h = fmaf(t1[d], w1r[u][d], h);
            unsigned m = __ballot_sync(0xFFFFFFFFu, h > 0.f);
            if (lane == 0) g_mask[node * 8 + u] = m;
            h = (h > 0.f) ? h : 0.f;
#pragma unroll
            for (int d = 0; d < 8; d++) acc[d] = fmaf(h, w2r[u][d], acc[d]);
        }
#pragma unroll
        for (int off = 16; off; off >>= 1)
#pragma unroll
            for (int d = 0; d < 8; d++) acc[d] += __shfl_xor_sync(0xFFFFFFFFu, acc[d], off);
        if (lane == 0) {
            float ns = g_norm_src[node];
            g_vn[node*2]   = make_float4(acc[0]*ns, acc[1]*ns, acc[2]*ns, acc[3]*ns);
            g_vn[node*2+1] = make_float4(acc[4]*ns, acc[5]*ns, acc[6]*ns, acc[7]*ns);
        }
        ca = na; cb = nb;
    }
}

// 6) h2 = (gather vn over in-edges)*ndst + b2 + q  → packed g_hm; 2 lanes/node
__global__ void k_agg2h2(const float* __restrict__ q, const float* __restrict__ b2, int n2) {
    int i = blockIdx.x * blockDim.x + threadIdx.x;
    bool ok = i < n2;
    int node = ok ? (i >> 1) : 0;
    int j = i & 1;
    float4 b2h = ((const float4*)b2)[j];
    float4 qv = make_float4(0,0,0,0);
    if (ok) qv = ((const float4*)q)[i];
    pdl_wait();
    int row = g_rowQ[node];
    int len = ok ? g_degin[node] : 0;
    float4 acc = make_float4(0.f, 0.f, 0.f, 0.f);
    for (int k = 0; k < len; k++) {
        int s = __ldg(&g_colQ[row + k]);
        acc = f4add(acc, __ldg(&g_vn[s*2 + j]));
    }
    if (!ok) return;
    g_hm[node*4 + j] = f4add(f4add(f4scale(acc, g_norm_dst[node]), b2h), qv);
}

// 7) G[n] = sum over incident edges c*(h2[other]-h2[n]); pair-split (R13 form:
//    shfls only at loop end, visits pipeline freely)
__global__ void k_GkC(const float* __restrict__ grav, int n2) {
    float gv = 0.5f * __ldg(grav);
    pdl_wait();
    int i = blockIdx.x * blockDim.x + threadIdx.x;
    bool ok = i < n2;
    int node = ok ? (i >> 1) : 0;
    int j = i & 1;
    float4 hn0 = g_hm[node*4],   hn1 = g_hm[node*4+1];
    float4 mn0 = g_hm[node*4+2], mn1 = g_hm[node*4+3];
    float a0=0,a1=0,a2=0,a3=0,a4=0,a5=0,a6=0,a7=0;
    int rowQ = g_rowQ[node], lenQ = ok ? g_degin[node]  : 0;
    int rowS = g_rowS[node], lenS = ok ? g_degout[node] : 0;
#pragma unroll 1
    for (int pass = 0; pass < 2; pass++) {
        int row = pass ? rowS : rowQ;
        int len = pass ? lenS : lenQ;
        const int* col = pass ? g_colS : g_colQ;
        for (int k = j; k < len; k += 2) {
            int o = __ldg(&col[row + k]);
            float4 ha = __ldg(&g_hm[o*4]),   hb = __ldg(&g_hm[o*4+1]);
            float4 ma = __ldg(&g_hm[o*4+2]), mb = __ldg(&g_hm[o*4+3]);
            float d0 = ha.x-hn0.x, d1 = ha.y-hn0.y, d2 = ha.z-hn0.z, d3 = ha.w-hn0.w;
            float d4 = hb.x-hn1.x, d5 = hb.y-hn1.y, d6 = hb.z-hn1.z, d7 = hb.w-hn1.w;
            float e2 = d0*d0+d1*d1+d2*d2+d3*d3+d4*d4+d5*d5+d6*d6+d7*d7;
            float sm = ma.x*mn0.x+ma.y*mn0.y+ma.z*mn0.z+ma.w*mn0.w
                     + mb.x*mn1.x+mb.y*mn1.y+mb.z*mn1.z+mb.w*mn1.w;
            float inv = rsqrtf(e2);
            float c = gv * sm * inv * inv * inv;
            a0 = fmaf(c, d0, a0); a1 = fmaf(c, d1, a1);
            a2 = fmaf(c, d2, a2); a3 = fmaf(c, d3, a3);
            a4 = fmaf(c, d4, a4); a5 = fmaf(c, d5, a5);
            a6 = fmaf(c, d6, a6); a7 = fmaf(c, d7, a7);
        }
    }
    a0 += __shfl_xor_sync(0xFFFFFFFFu, a0, 1);
    a1 += __shfl_xor_sync(0xFFFFFFFFu, a1, 1);
    a2 += __shfl_xor_sync(0xFFFFFFFFu, a2, 1);
    a3 += __shfl_xor_sync(0xFFFFFFFFu, a3, 1);
    a4 += __shfl_xor_sync(0xFFFFFFFFu, a4, 1);
    a5 += __shfl_xor_sync(0xFFFFFFFFu, a5, 1);
    a6 += __shfl_xor_sync(0xFFFFFFFFu, a6, 1);
    a7 += __shfl_xor_sync(0xFFFFFFFFu, a7, 1);
    if (!ok) return;
    float4 acc = j ? make_float4(a4,a5,a6,a7) : make_float4(a0,a1,a2,a3);
    g_G[i]  = acc;
    g_Gn[i] = f4scale(acc, g_norm_dst[node]);
}

// 8) rn[n] = (sum over out-edges Gn[dst]) * nsrc ; 2 lanes/node
__global__ void k_aggRN(int n2) {
    pdl_wait();
    int i = blockIdx.x * blockDim.x + threadIdx.x;
    bool ok = i < n2;
    int node = ok ? (i >> 1) : 0;
    int j = i & 1;
    int row = g_rowS[node];
    int len = ok ? g_degout[node] : 0;
    float4 acc = make_float4(0.f, 0.f, 0.f, 0.f);
    for (int k = 0; k < len; k++) {
        int u = __ldg(&g_colS[row + k]);
        acc = f4add(acc, __ldg(&g_Gn[u*2 + j]));
    }
    if (!ok) return;
    g_rn[i] = f4scale(acc, g_norm_src[node]);
}

// 9) MLP bwd: register weights, 148 blocks, prefetch, writes zzn
__global__ __launch_bounds__(256) void k_mlp_bwd(
        const float* __restrict__ W1v, const float* __restrict__ W2v,
        int n, int totalWarps) {
    int tid = blockIdx.x * blockDim.x + threadIdx.x;
    int gw = tid >> 5, lane = tid & 31;

    float w1r[8][8], w2r[8][8];
#pragma unroll
    for (int u = 0; u < 8; u++) {
        int j = u * 32 + lane;
#pragma unroll
        for (int d = 0; d < 8; d++) w1r[u][d] = __ldg(&W1v[d * HDIM + j]);
        float4 wa = __ldg((const float4*)(W2v + j * 8));
        float4 wb = __ldg((const float4*)(W2v + j * 8 + 4));
        w2r[u][0] = wa.x; w2r[u][1] = wa.y; w2r[u][2] = wa.z; w2r[u][3] = wa.w;
        w2r[u][4] = wb.x; w2r[u][5] = wb.y; w2r[u][6] = wb.z; w2r[u][7] = wb.w;
    }
    pdl_wait();

    int node = gw;
    float4 ca = make_float4(0,0,0,0), cb = ca;
    unsigned cm[8] = {0,0,0,0,0,0,0,0};
    if (node < n) {
        ca = __ldg(&g_rn[node*2]); cb = __ldg(&g_rn[node*2+1]);
#pragma unroll
        for (int u = 0; u < 8; u++) cm[u] = __ldg(&g_mask[node*8+u]);
    }
    for (; node < n; node += totalWarps) {
        int nxt = node + totalWarps;
        float4 na = make_float4(0,0,0,0), nb = na;
        unsigned nm[8] = {0,0,0,0,0,0,0,0};
        if (nxt < n) {
            na = __ldg(&g_rn[nxt*2]); nb = __ldg(&g_rn[nxt*2+1]);
#pragma unroll
            for (int u = 0; u < 8; u++) nm[u] = __ldg(&g_mask[nxt*8+u]);
        }
        float rr[8] = {ca.x, ca.y, ca.z, ca.w, cb.x, cb.y, cb.z, cb.w};
        float acc[8] = {0.f,0.f,0.f,0.f,0.f,0.f,0.f,0.f};
#pragma unroll
        for (int u = 0; u < 8; u++) {
            float gh = 0.f;
#pragma unroll
            for (int d = 0; d < 8; d++) gh = fmaf(rr[d], w2r[u][d], gh);
            float gu = ((cm[u] >> lane) & 1u) ? gh : 0.f;
#pragma unroll
            for (int d = 0; d < 8; d++) acc[d] = fmaf(gu, w1r[u][d], acc[d]);
        }
#pragma unroll
        for (int off = 16; off; off >>= 1)
#pragma unroll
            for (int d = 0; d < 8; d++) acc[d] += __shfl_xor_sync(0xFFFFFFFFu, acc[d], off);
        if (lane == 0) {
            float ndst = g_norm_dst[node];
            g_zzn[node*2]   = make_float4(acc[0]*ndst, acc[1]*ndst, acc[2]*ndst, acc[3]*ndst);
            g_zzn[node*2+1] = make_float4(acc[4]*ndst, acc[5]*ndst, acc[6]*ndst, acc[7]*ndst);
        }
        ca = na; cb = nb;
#pragma unroll
        for (int u = 0; u < 8; u++) cm[u] = nm[u];
    }
}

// 10) w = gather zzn over out-edges; out = G + nsrc*w ; 2 lanes/node; reset state
__global__ void k_wfinal(float4* __restrict__ out4, int n2) {
    pdl_wait();
    int i = blockIdx.x * blockDim.x + threadIdx.x;
    bool ok = i < n2;
    int node = ok ? (i >> 1) : 0;
    int j = i & 1;
    int row = g_rowS[node];
    int len = ok ? g_degout[node] : 0;
    float4 acc = make_float4(0.f, 0.f, 0.f, 0.f);
    for (int k = 0; k < len; k++) {
        int u = __ldg(&g_colS[row + k]);
        acc = f4add(acc, __ldg(&g_zzn[u*2 + j]));
    }
    if (i == 0) { g_ctrQ = 0; g_ctrS = 0; }
    if (!ok) return;
    float ns = g_norm_src[node];
    out4[node*4 + j] = f4add(g_G[node*2 + j], f4scale(acc, ns));
    if (j == 0) g_degin[node] = 0; else g_degout[node] = 0;
}

// ---- host: PDL launches ----
template <typename K, typename... Args>
static inline void launch_pdl(K kern, int grid, int block, Args... args) {
    cudaLaunchConfig_t cfg = {};
    cfg.gridDim = dim3(grid);
    cfg.blockDim = dim3(block);
    cudaLaunchAttribute attr[1];
    attr[0].id = cudaLaunchAttributeProgrammaticStreamSerialization;
    attr[0].val.programmaticStreamSerializationAllowed = 1;
    cfg.attrs = attr;
    cfg.numAttrs = 1;
    cudaLaunchKernelEx(&cfg, kern, args...);
}

extern "C" void kernel_launch(void* const* d_in, const int* in_sizes, int n_in,
                              void* d_out, int out_size) {
    const float* q    = (const float*)d_in[0];
    const float* p    = (const float*)d_in[1];
    const float* M    = (const float*)d_in[2];
    const int*   src  = (const int*)  d_in[3];
    const int*   dst  = (const int*)  d_in[4];
    const float* W1   = (const float*)d_in[5];
    const float* b1   = (const float*)d_in[6];
    const float* W2   = (const float*)d_in[7];
    const float* b2   = (const float*)d_in[8];
    const float* grav = (const float*)d_in[9];
    float4* out4 = (float4*)d_out;

    int N = in_sizes[0] / DDIM;
    int E = in_sizes[3];
    if (N > NN || E > EE) return;

    int n2  = N * 2;
    int gN  = (N + 255) / 256;
    int gN2 = (n2 + 255) / 256;
    int gE  = (E + 255) / 256;
    int gE2 = (E * 2 + 255) / 256;

    // MLP: 182 regs → hard cap 1 block/SM. 148 blocks = exactly one wave.
    int mlpBlocks = 148;
    int mlpWarps  = mlpBlocks * 8;

    k_deg<<<gE, 256>>>(src, dst, E);
    launch_pdl(k_prep,    gN,   256, p, M, q, out4, N);
    launch_pdl(k_fill,    gE2,  256, src, dst, E);
    launch_pdl(k_aggT1,   gN2,  256, n2);
    launch_pdl(k_mlp_fwd, mlpBlocks, 256, W1, b1, W2, N, mlpWarps);
    launch_pdl(k_agg2h2,  gN2,  256, q, b2, n2);
    launch_pdl(k_GkC,     gN2,  256, grav, n2);
    launch_pdl(k_aggRN,   gN2,  256, n2);
    launch_pdl(k_mlp_bwd, mlpBlocks, 256, W1, W2, N, mlpWarps);
    launch_pdl(k_wfinal,  gN2,  256, out4, n2);
}

// round 16
// speedup vs baseline: 1.2255x; 1.0025x over previous
#include <cuda_runtime.h>

#define NN 100000
#define EE 1600000
#define DDIM 8
#define HDIM 256

// ---- node data ----
__device__ float4 g_qn  [NN*2];   // q * norm_src
__device__ float4 g_t1  [NN*2];   // (gathered qn) * norm_dst
__device__ float4 g_vn  [NN*2];   // v * norm_src
__device__ float4 g_hm  [NN*4];   // packed per node: h2[0], h2[1], md[0], md[1]
__device__ float4 g_G   [NN*2];
__device__ float4 g_Gn  [NN*2];   // G * norm_dst
__device__ float4 g_rn  [NN*2];   // (gathered Gn) * norm_src
__device__ float4 g_zzn [NN*2];   // zz * norm_dst
__device__ float  g_norm_src[NN];
__device__ float  g_norm_dst[NN];
__device__ unsigned g_mask[NN*DDIM];
// ---- CSR (zero at load; counters restored each call) ----
__device__ int   g_degout[NN], g_degin[NN];
__device__ int   g_rowQ[NN], g_rowS[NN];
__device__ int   g_curQ[NN], g_curS[NN];
__device__ int   g_colQ[EE];
__device__ int   g_colS[EE];
__device__ int   g_ctrQ, g_ctrS;

__device__ __forceinline__ float4 f4add(float4 a, float4 b) {
    return make_float4(a.x+b.x, a.y+b.y, a.z+b.z, a.w+b.w);
}
__device__ __forceinline__ float4 f4scale(float4 a, float s) {
    return make_float4(a.x*s, a.y*s, a.z*s, a.w*s);
}
__device__ __forceinline__ void pdl_wait() { cudaGridDependencySynchronize(); }

// 1) degree count
__global__ void k_deg(const int* __restrict__ src, const int* __restrict__ dst, int E) {
    int e = blockIdx.x * blockDim.x + threadIdx.x;
    if (e >= E) return;
    atomicAdd(&g_degout[src[e]], 1);
    atomicAdd(&g_degin [dst[e]], 1);
}

// 2) norms, CSR row alloc, md (packed into hm), qn, dHdP
__global__ void k_prep(const float* __restrict__ p, const float* __restrict__ M,
                       const float* __restrict__ q, float4* __restrict__ out4, int n) {
    int nd = blockIdx.x * blockDim.x + threadIdx.x;
    int lane = threadIdx.x & 31;
    bool act = nd < n;
    float md[8];
    float4 qa = make_float4(0,0,0,0), qb = qa, pa = qa, pb = qa;
    if (act) {
        const float* Mr = M + (long long)nd * 64;
#pragma unroll
        for (int d = 0; d < 8; d++) md[d] = Mr[d * 9];
        const float4* q4 = (const float4*)q;
        const float4* p4 = (const float4*)p;
        qa = q4[nd*2]; qb = q4[nd*2+1];
        pa = p4[nd*2]; pb = p4[nd*2+1];
    }
    pdl_wait();
    int din  = act ? g_degin[nd]  : 0;
    int dout = act ? g_degout[nd] : 0;
    int sin = din, sout = dout;
#pragma unroll
    for (int o = 1; o < 32; o <<= 1) {
        int t1 = __shfl_up_sync(0xFFFFFFFFu, sin,  o); if (lane >= o) sin  += t1;
        int t2 = __shfl_up_sync(0xFFFFFFFFu, sout, o); if (lane >= o) sout += t2;
    }
    int baseQ = 0, baseS = 0;
    if (lane == 31) {
        baseQ = atomicAdd(&g_ctrQ, sin);
        baseS = atomicAdd(&g_ctrS, sout);
    }
    baseQ = __shfl_sync(0xFFFFFFFFu, baseQ, 31);
    baseS = __shfl_sync(0xFFFFFFFFu, baseS, 31);
    if (!act) return;
    int rowQ = baseQ + sin - din;
    int rowS = baseS + sout - dout;
    g_rowQ[nd] = rowQ; g_curQ[nd] = rowQ;
    g_rowS[nd] = rowS; g_curS[nd] = rowS;

    float nsrc = (dout > 0) ? rsqrtf((float)dout) : 1.0f;
    float ndst = (din  > 0) ? rsqrtf((float)din)  : 1.0f;
    g_norm_src[nd] = nsrc;
    g_norm_dst[nd] = ndst;
    g_hm[nd*4+2] = make_float4(md[0], md[1], md[2], md[3]);
    g_hm[nd*4+3] = make_float4(md[4], md[5], md[6], md[7]);
    g_qn[nd*2]   = f4scale(qa, nsrc);
    g_qn[nd*2+1] = f4scale(qb, nsrc);
    out4[nd*4+2] = make_float4(pa.x/md[0], pa.y/md[1], pa.z/md[2], pa.w/md[3]);
    out4[nd*4+3] = make_float4(pb.x/md[4], pb.y/md[5], pb.z/md[6], pb.w/md[7]);
}

// 3) build both CSRs — 2 threads per edge (one per side)
__global__ void k_fill(const int* __restrict__ src, const int* __restrict__ dst, int E) {
    int t = blockIdx.x * blockDim.x + threadIdx.x;
    int e = t >> 1, side = t & 1;
    int s = 0, u = 0;
    bool act = e < E;
    if (act) { s = src[e]; u = dst[e]; }
    pdl_wait();
    if (!act) return;
    if (side == 0) g_colQ[atomicAdd(&g_curQ[u], 1)] = s;
    else           g_colS[atomicAdd(&g_curS[s], 1)] = u;
}

// 4) t1[n] = (sum over in-edges qn[src]) * ndst ; 2 lanes/node, half-record each
__global__ void k_aggT1(int n2) {
    pdl_wait();
    int i = blockIdx.x * blockDim.x + threadIdx.x;
    bool ok = i < n2;
    int node = ok ? (i >> 1) : 0;
    int j = i & 1;
    int row = g_rowQ[node];
    int len = ok ? g_degin[node] : 0;
    float4 acc = make_float4(0.f, 0.f, 0.f, 0.f);
    for (int k = 0; k < len; k++) {
        int s = __ldg(&g_colQ[row + k]);
        acc = f4add(acc, __ldg(&g_qn[s*2 + j]));
    }
    if (!ok) return;
    g_t1[i] = f4scale(acc, g_norm_dst[node]);
}

// 5) MLP fwd: register weights (1 block/SM cap — 148 blocks = exactly 1 wave)
__global__ __launch_bounds__(256) void k_mlp_fwd(
        const float* __restrict__ W1v, const float* __restrict__ b1v,
        const float* __restrict__ W2v, int n, int totalWarps) {
    int tid = blockIdx.x * blockDim.x + threadIdx.x;
    int gw = tid >> 5, lane = tid & 31;

    float w1r[8][8], w2r[8][8], b1r[8];
#pragma unroll
    for (int u = 0; u < 8; u++) {
        int j = u * 32 + lane;
#pragma unroll
        for (int d = 0; d < 8; d++) w1r[u][d] = __ldg(&W1v[d * HDIM + j]);
        float4 wa = __ldg((const float4*)(W2v + j * 8));
        float4 wb = __ldg((const float4*)(W2v + j * 8 + 4));
        w2r[u][0] = wa.x; w2r[u][1] = wa.y; w2r[u][2] = wa.z; w2r[u][3] = wa.w;
        w2r[u][4] = wb.x; w2r[u][5] = wb.y; w2r[u][6] = wb.z; w2r[u][7] = wb.w;
        b1r[u] = __ldg(&b1v[j]);
    }
    pdl_wait();

    int node = gw;
    float4 ca = make_float4(0,0,0,0), cb = ca;
    if (node < n) { ca = __ldg(&g_t1[node*2]); cb = __ldg(&g_t1[node*2+1]); }
    for (; node < n; node += totalWarps) {
        int nxt = node + totalWarps;
        float4 na = make_float4(0,0,0,0), nb = na;
        if (nxt < n) { na = __ldg(&g_t1[nxt*2]); nb = __ldg(&g_t1[nxt*2+1]); }
        float t1[8] = {ca.x, ca.y, ca.z, ca.w, cb.x, cb.y, cb.z, cb.w};
        float acc[8] = {0.f,0.f,0.f,0.f,0.f,0.f,0.f,0.f};
#pragma unroll
        for (int u = 0; u < 8; u++) {
            float h = b1r[u];
#pragma unroll
            for (int d = 0; d < 8; d++) h = fmaf(t1[d], w1r[u][d], h);
            unsigned m = __ballot_sync(0xFFFFFFFFu, h > 0.f);
            if (lane == 0) g_mask[node * 8 + u] = m;
            h = (h > 0.f) ? h : 0.f;
#pragma unroll
            for (int d = 0; d < 8; d++) acc[d] = fmaf(h, w2r[u][d], acc[d]);
        }
#pragma unroll
        for (int off = 16; off; off >>= 1)
#pragma unroll
            for (int d = 0; d < 8; d++) acc[d] += __shfl_xor_sync(0xFFFFFFFFu, acc[d], off);
        if (lane == 0) {
            float ns = g_norm_src[node];
            g_vn[node*2]   = make_float4(acc[0]*ns, acc[1]*ns, acc[2]*ns, acc[3]*ns);
            g_vn[node*2+1] = make_float4(acc[4]*ns, acc[5]*ns, acc[6]*ns, acc[7]*ns);
        }
        ca = na; cb = nb;
    }
}

// 6) h2 = (gather vn over in-edges)*ndst + b2 + q  → packed g_hm; 2 lanes/node
__global__ void k_agg2h2(const float* __restrict__ q, const float* __restrict__ b2, int n2) {
    int i = blockIdx.x * blockDim.x + threadIdx.x;
    bool ok = i < n2;
    int node = ok ? (i >> 1) : 0;
    int j = i & 1;
    float4 b2h = ((const float4*)b2)[j];
    float4 qv = make_float4(0,0,0,0);
    if (ok) qv = ((const float4*)q)[i];
    pdl_wait();
    int row = g_rowQ[node];
    int len = ok ? g_degin[node] : 0;
    float4 acc = make_float4(0.f, 0.f, 0.f, 0.f);
    for (int k = 0; k < len; k++) {
        int s = __ldg(&g_colQ[row + k]);
        acc = f4add(acc, __ldg(&g_vn[s*2 + j]));
    }
    if (!ok) return;
    g_hm[node*4 + j] = f4add(f4add(f4scale(acc, g_norm_dst[node]), b2h), qv);
}

// 7) G[n] = sum over incident edges c*(h2[other]-h2[n])
//    2 lanes per node; each lane loads ONLY its half's 2 float4s of the 64B
//    record (same 128B line as partner → 1 payload line/visit). Per-visit
//    pair shfl exchanges the e2/sm partials; each lane owns its output half.
__global__ void k_GkC(const float* __restrict__ grav, int n2) {
    float gv = 0.5f * __ldg(grav);
    pdl_wait();
    int i = blockIdx.x * blockDim.x + threadIdx.x;
    int lane = threadIdx.x & 31;
    unsigned pmask = 3u << (lane & 30);          // the 2 lanes of this node-pair
    bool ok = i < n2;
    int node = ok ? (i >> 1) : 0;
    int j = i & 1;
    float4 hn = g_hm[node*4 + j];                // own h2 half
    float4 mn = g_hm[node*4 + 2 + j];            // own md half
    float a0 = 0.f, a1 = 0.f, a2 = 0.f, a3 = 0.f;
    int rowQ = g_rowQ[node], lenQ = ok ? g_degin[node]  : 0;
    int rowS = g_rowS[node], lenS = ok ? g_degout[node] : 0;
#pragma unroll 1
    for (int pass = 0; pass < 2; pass++) {
        int row = pass ? rowS : rowQ;
        int len = pass ? lenS : lenQ;
        const int* col = pass ? g_colS : g_colQ;
#pragma unroll 2
        for (int k = 0; k < len; k++) {
            int o = __ldg(&col[row + k]);
            float4 hv = __ldg(&g_hm[o*4 + j]);       // neighbor h2 half
            float4 mv = __ldg(&g_hm[o*4 + 2 + j]);   // neighbor md half
            float d0 = hv.x - hn.x, d1 = hv.y - hn.y;
            float d2 = hv.z - hn.z, d3 = hv.w - hn.w;
            float e2h = d0*d0 + d1*d1 + d2*d2 + d3*d3;
            float smh = mv.x*mn.x + mv.y*mn.y + mv.z*mn.z + mv.w*mn.w;
            float e2 = e2h + __shfl_xor_sync(pmask, e2h, 1);
            float sm = smh + __shfl_xor_sync(pmask, smh, 1);
            float inv = rsqrtf(e2);
            float c = gv * sm * inv * inv * inv;
            a0 = fmaf(c, d0, a0); a1 = fmaf(c, d1, a1);
            a2 = fmaf(c, d2, a2); a3 = fmaf(c, d3, a3);
        }
    }
    if (!ok) return;
    float nd = g_norm_dst[node];
    g_G [i] = make_float4(a0, a1, a2, a3);
    g_Gn[i] = make_float4(a0*nd, a1*nd, a2*nd, a3*nd);
}

// 8) rn[n] = (sum over out-edges Gn[dst]) * nsrc ; 2 lanes/node
__global__ void k_aggRN(int n2) {
    pdl_wait();
    int i = blockIdx.x * blockDim.x + threadIdx.x;
    bool ok = i < n2;
    int node = ok ? (i >> 1) : 0;
    int j = i & 1;
    int row = g_rowS[node];
    int len = ok ? g_degout[node] : 0;
    float4 acc = make_float4(0.f, 0.f, 0.f, 0.f);
    for (int k = 0; k < len; k++) {
        int u = __ldg(&g_colS[row + k]);
        acc = f4add(acc, __ldg(&g_Gn[u*2 + j]));
    }
    if (!ok) return;
    g_rn[i] = f4scale(acc, g_norm_src[node]);
}

// 9) MLP bwd: register weights, 148 blocks, prefetch, writes zzn
__global__ __launch_bounds__(256) void k_mlp_bwd(
        const float* __restrict__ W1v, const float* __restrict__ W2v,
        int n, int totalWarps) {
    int tid = blockIdx.x * blockDim.x + threadIdx.x;
    int gw = tid >> 5, lane = tid & 31;

    float w1r[8][8], w2r[8][8];
#pragma unroll
    for (int u = 0; u < 8; u++) {
        int j = u * 32 + lane;
#pragma unroll
        for (int d = 0; d < 8; d++) w1r[u][d] = __ldg(&W1v[d * HDIM + j]);
        float4 wa = __ldg((const float4*)(W2v + j * 8));
        float4 wb = __ldg((const float4*)(W2v + j * 8 + 4));
        w2r[u][0] = wa.x; w2r[u][1] = wa.y; w2r[u][2] = wa.z; w2r[u][3] = wa.w;
        w2r[u][4] = wb.x; w2r[u][5] = wb.y; w2r[u][6] = wb.z; w2r[u][7] = wb.w;
    }
    pdl_wait();

    int node = gw;
    float4 ca = make_float4(0,0,0,0), cb = ca;
    unsigned cm[8] = {0,0,0,0,0,0,0,0};
    if (node < n) {
        ca = __ldg(&g_rn[node*2]); cb = __ldg(&g_rn[node*2+1]);
#pragma unroll
        for (int u = 0; u < 8; u++) cm[u] = __ldg(&g_mask[node*8+u]);
    }
    for (; node < n; node += totalWarps) {
        int nxt = node + totalWarps;
        float4 na = make_float4(0,0,0,0), nb = na;
        unsigned nm[8] = {0,0,0,0,0,0,0,0};
        if (nxt < n) {
            na = __ldg(&g_rn[nxt*2]); nb = __ldg(&g_rn[nxt*2+1]);
#pragma unroll
            for (int u = 0; u < 8; u++) nm[u] = __ldg(&g_mask[nxt*8+u]);
        }
        float rr[8] = {ca.x, ca.y, ca.z, ca.w, cb.x, cb.y, cb.z, cb.w};
        float acc[8] = {0.f,0.f,0.f,0.f,0.f,0.f,0.f,0.f};
#pragma unroll
        for (int u = 0; u < 8; u++) {
            float gh = 0.f;
#pragma unroll
            for (int d = 0; d < 8; d++) gh = fmaf(rr[d], w2r[u][d], gh);
            float gu = ((cm[u] >> lane) & 1u) ? gh : 0.f;
#pragma unroll
            for (int d = 0; d < 8; d++) acc[d] = fmaf(gu, w1r[u][d], acc[d]);
        }
#pragma unroll
        for (int off = 16; off; off >>= 1)
#pragma unroll
            for (int d = 0; d < 8; d++) acc[d] += __shfl_xor_sync(0xFFFFFFFFu, acc[d], off);
        if (lane == 0) {
            float ndst = g_norm_dst[node];
            g_zzn[node*2]   = make_float4(acc[0]*ndst, acc[1]*ndst, acc[2]*ndst, acc[3]*ndst);
            g_zzn[node*2+1] = make_float4(acc[4]*ndst, acc[5]*ndst, acc[6]*ndst, acc[7]*ndst);
        }
        ca = na; cb = nb;
#pragma unroll
        for (int u = 0; u < 8; u++) cm[u] = nm[u];
    }
}

// 10) w = gather zzn over out-edges; out = G + nsrc*w ; 2 lanes/node; reset state
__global__ void k_wfinal(float4* __restrict__ out4, int n2) {
    pdl_wait();
    int i = blockIdx.x * blockDim.x + threadIdx.x;
    bool ok = i < n2;
    int node = ok ? (i >> 1) : 0;
    int j = i & 1;
    int row = g_rowS[node];
    int len = ok ? g_degout[node] : 0;
    float4 acc = make_float4(0.f, 0.f, 0.f, 0.f);
    for (int k = 0; k < len; k++) {
        int u = __ldg(&g_colS[row + k]);
        acc = f4add(acc, __ldg(&g_zzn[u*2 + j]));
    }
    if (i == 0) { g_ctrQ = 0; g_ctrS = 0; }
    if (!ok) return;
    float ns = g_norm_src[node];
    out4[node*4 + j] = f4add(g_G[i], f4scale(acc, ns));
    if (j == 0) g_degin[node] = 0; else g_degout[node] = 0;
}

// ---- host: PDL launches ----
template <typename K, typename... Args>
static inline void launch_pdl(K kern, int grid, int block, Args... args) {
    cudaLaunchConfig_t cfg = {};
    cfg.gridDim = dim3(grid);
    cfg.blockDim = dim3(block);
    cudaLaunchAttribute attr[1];
    attr[0].id = cudaLaunchAttributeProgrammaticStreamSerialization;
    attr[0].val.programmaticStreamSerializationAllowed = 1;
    cfg.attrs = attr;
    cfg.numAttrs = 1;
    cudaLaunchKernelEx(&cfg, kern, args...);
}

extern "C" void kernel_launch(void* const* d_in, const int* in_sizes, int n_in,
                              void* d_out, int out_size) {
    const float* q    = (const float*)d_in[0];
    const float* p    = (const float*)d_in[1];
    const float* M    = (const float*)d_in[2];
    const int*   src  = (const int*)  d_in[3];
    const int*   dst  = (const int*)  d_in[4];
    const float* W1   = (const float*)d_in[5];
    const float* b1   = (const float*)d_in[6];
    const float* W2   = (const float*)d_in[7];
    const float* b2   = (const float*)d_in[8];
    const float* grav = (const float*)d_in[9];
    float4* out4 = (float4*)d_out;

    int N = in_sizes[0] / DDIM;
    int E = in_sizes[3];
    if (N > NN || E > EE) return;

    int n2  = N * 2;
    int gN  = (N + 255) / 256;
    int gN2 = (n2 + 255) / 256;
    int gE  = (E + 255) / 256;
    int gE2 = (E * 2 + 255) / 256;

    // MLP: 182 regs → hard cap 1 block/SM. 148 blocks = exactly one wave.
    int mlpBlocks = 148;
    int mlpWarps  = mlpBlocks * 8;

    k_deg<<<gE, 256>>>(src, dst, E);
    launch_pdl(k_prep,    gN,   256, p, M, q, out4, N);
    launch_pdl(k_fill,    gE2,  256, src, dst, E);
    launch_pdl(k_aggT1,   gN2,  256, n2);
    launch_pdl(k_mlp_fwd, mlpBlocks, 256, W1, b1, W2, N, mlpWarps);
    launch_pdl(k_agg2h2,  gN2,  256, q, b2, n2);
    launch_pdl(k_GkC,     gN2,  256, grav, n2);
    launch_pdl(k_aggRN,   gN2,  256, n2);
    launch_pdl(k_mlp_bwd, mlpBlocks, 256, W1, W2, N, mlpWarps);
    launch_pdl(k_wfinal,  gN2,  256, out4, n2);
}